// round 16
// baseline (speedup 1.0000x reference)
#include <cuda_runtime.h>
#include <cuda_fp16.h>
#include <math_constants.h>
#include <cstdint>

// Problem constants
#define DD 256
#define TT 4096
#define BBATCH 16
#define KK 1024
#define NTOK (BBATCH * TT)                  // 65536 tokens
#define NDATA ((size_t)BBATCH * DD * TT)    // 16777216 output data elements
#define CAP 8

// Scratch (no cudaMalloc allowed)
__device__ float          g_e2[KK];
__device__ float          g_r2[NTOK];
__device__ int            g_idx[NTOK];
__device__ double         g_loss_sum;
__device__ float          g_zt[NDATA];          // z transposed [token][d] fp32
__device__ __half         g_zh[NDATA];          // z transposed fp16
__device__ __half         g_eh[KK * DD];        // emb fp16
__device__ unsigned short g_cand[(size_t)NTOK * CAP];
__device__ unsigned char  g_ncand[NTOK];        // 255 => overflow -> full scan

__device__ __forceinline__ uint32_t s2u(const void* p) {
    uint32_t a;
    asm("{ .reg .u64 t; cvta.to.shared.u64 t, %1; cvt.u32.u64 %0, t; }"
        : "=r"(a) : "l"(p));
    return a;
}

#define LDSM_X4(r0, r1, r2, r3, addr)                                          \
    asm volatile("ldmatrix.sync.aligned.m8n8.x4.shared.b16 {%0,%1,%2,%3}, [%4];" \
                 : "=r"(r0), "=r"(r1), "=r"(r2), "=r"(r3) : "r"(addr))

// fp16 HMMA (validated R14/R15), u=2^-11.
#define MMA16816(d, a0, a1, a2, a3, b0, b1)                                    \
    asm volatile("mma.sync.aligned.m16n8k16.row.col.f32.f16.f16.f32 "          \
                 "{%0,%1,%2,%3}, {%4,%5,%6,%7}, {%8,%9}, {%0,%1,%2,%3};"       \
                 : "+f"((d)[0]), "+f"((d)[1]), "+f"((d)[2]), "+f"((d)[3])      \
                 : "r"(a0), "r"(a1), "r"(a2), "r"(a3), "r"(b0), "r"(b1))

#define CP_ASYNC16(dst, src)                                                   \
    asm volatile("cp.async.cg.shared.global [%0], [%1], 16;"                   \
                 :: "r"(dst), "l"(src))
#define CP_COMMIT() asm volatile("cp.async.commit_group;" ::: "memory")
#define CP_WAIT0()  asm volatile("cp.async.wait_group 0;" ::: "memory")

// Exact rescore of one code: sequential ascending-d fused fmaf (bit-matches
// the reference; validated R2/R7/R13/R14/R15).
__device__ __forceinline__ float exact_dist(const float* __restrict__ zr,
                                            const float* __restrict__ er,
                                            float r2, float e2) {
    float acc = 0.0f;
    #pragma unroll 8
    for (int d = 0; d < DD; d += 4) {
        float4 z4 = *(const float4*)&zr[d];
        float4 e4 = __ldg((const float4*)&er[d]);
        acc = fmaf(z4.x, e4.x, acc);
        acc = fmaf(z4.y, e4.y, acc);
        acc = fmaf(z4.z, e4.z, acc);
        acc = fmaf(z4.w, e4.w, acc);
    }
    return __fsub_rn(__fadd_rn(r2, e2), __fmul_rn(2.0f, acc));
}

// ===========================================================================
// Kernel 0: exact ||e_k||^2 (sequential mul-then-add) + fp16 convert + zero loss
// ===========================================================================
__global__ void vq_prep_kernel(const float* __restrict__ emb) {
    int k = blockIdx.x * blockDim.x + threadIdx.x;
    if (k == 0) g_loss_sum = 0.0;
    if (k < KK) {
        const float* e = emb + (size_t)k * DD;
        float acc = 0.0f;
        #pragma unroll 8
        for (int d = 0; d < DD; ++d) {
            float v = e[d];
            acc = __fadd_rn(acc, __fmul_rn(v, v));
            g_eh[(size_t)k * DD + d] = __float2half_rn(v);
        }
        g_e2[k] = acc;
    }
}

// ===========================================================================
// Kernel 1: FUSED transpose (zt fp32 + zh fp16) + exact r2 (R15 winner).
// ===========================================================================
__global__ void __launch_bounds__(256) vq_convert_r2_kernel(const float* __restrict__ z) {
    __shared__ float tile[256][33];
    const int b = blockIdx.x >> 7, t0 = (blockIdx.x & 127) << 5;
    const int tid = threadIdx.x;
    const int tx = tid & 31, ty = tid >> 5;           // 32 x 8
    const float* src = z + (size_t)b * DD * TT + t0;
    #pragma unroll
    for (int k = 0; k < 32; ++k) {
        int d = ty + (k << 3);
        tile[d][tx] = src[(size_t)d * TT + tx];
    }
    __syncthreads();

    const int tok = tid >> 3, q = tid & 7;
    const size_t base = ((size_t)((b << 12) + t0 + tok)) * DD;
    #pragma unroll
    for (int jj = 0; jj < 8; ++jj) {
        int d0 = (jj << 5) + (q << 2);
        float4 v = make_float4(tile[d0][tok], tile[d0 + 1][tok],
                               tile[d0 + 2][tok], tile[d0 + 3][tok]);
        *(float4*)&g_zt[base + d0] = v;
        __half2 h01 = __floats2half2_rn(v.x, v.y);
        __half2 h23 = __floats2half2_rn(v.z, v.w);
        *(__half2*)&g_zh[base + d0]     = h01;
        *(__half2*)&g_zh[base + d0 + 2] = h23;
    }

    if (tid < 32) {
        float acc = 0.0f;
        #pragma unroll 8
        for (int d = 0; d < DD; ++d) {
            float v = tile[d][tid];
            acc = __fadd_rn(acc, __fmul_rn(v, v));
        }
        g_r2[(b << 12) + t0 + tid] = acc;
    }
}

// ===========================================================================
// Kernel 2: fp16 HMMA GEMM + IN-KERNEL candidate filter.
// Core (tiles, cp.async double-buffered B, fragment maps, fp16 da epilogue
// arithmetic) is byte-identical to the R14/R15 winner. Scores go to a 16.9KB
// smem buffer in two 64-col half-passes instead of DRAM; 128 filter threads
// (1/token) run the sequential running-min + cap-8 candidate append with
// compaction-on-full (R6-validated; containment: the true argmin always
// appends and is never compacted since best only decreases). Margin is the
// R14-validated fp16 bound. Overflow -> g_ncand=255 (warp-parallel full-scan
// fallback downstream, R13-validated).
// ===========================================================================
#define ES2_OFF 0                      // 4096 B
#define A_OFF   4096                   // 65536 B
#define B0_OFF  69632                  // 65536 B
#define B1_OFF  135168                 // 65536 B
#define S_OFF   200704                 // 128*66*2 = 16896 B
#define CV_OFF  217600                 // 128*8*4 = 4096 B
#define CC_OFF  221696                 // 128*8*2 = 2048 B
#define SMEM_TOT 223744
#define S_STRIDE 66

__global__ void __launch_bounds__(512, 1) vq_mma_kernel() {
    extern __shared__ char smem[];
    const uint32_t sb = s2u(smem);
    const int tid = threadIdx.x, wid = tid >> 5, lane = tid & 31;
    const int tok0 = blockIdx.x << 7;
    float* es2s = (float*)(smem + ES2_OFF);
    __half* S   = (__half*)(smem + S_OFF);
    float* cval = (float*)(smem + CV_OFF);
    unsigned short* ccode = (unsigned short*)(smem + CC_OFF);

    es2s[tid]       = g_e2[tid];
    es2s[tid + 512] = g_e2[tid + 512];

    // Filter state (token tid owned by threads 0..127).
    float best = CUDART_INF_F, margin = 0.0f;
    int ncand = 0;
    bool ovf = false;
    if (tid < 128) margin = fmaf(8e-5f, sqrtf(g_r2[tok0 + tid]), 6e-4f);

    const uint4* zsrc = (const uint4*)(g_zh + ((size_t)tok0 << 8));
    #pragma unroll 2
    for (int i = tid; i < 4096; i += 512) {
        int row = i >> 5, kb = i & 31;
        CP_ASYNC16(sb + A_OFF + row * 512 + ((kb ^ (row & 7)) << 4), zsrc + i);
    }
    {
        const uint4* esrc = (const uint4*)g_eh;
        #pragma unroll 2
        for (int i = tid; i < 4096; i += 512) {
            int row = i >> 5, kb = i & 31;
            CP_ASYNC16(sb + B0_OFF + row * 512 + ((kb ^ (row & 7)) << 4), esrc + i);
        }
    }
    CP_COMMIT();
    CP_WAIT0();
    __syncthreads();

    const int rg = wid & 7, ch = wid >> 3;
    const int m0 = rg << 4, nb0 = ch << 6;
    const int lr = lane & 7;
    const int arow = m0 + lr + (((lane >> 3) & 1) << 3);
    const int akc  = lane >> 4;
    const int brow_off = lr + ((lane >> 4) << 3);
    const int bkc  = (lane >> 3) & 1;
    const uint32_t aBase = sb + A_OFF + (uint32_t)arow * 512;

    for (int c = 0; c < 8; ++c) {
        const int nc0 = c << 7;
        const uint32_t bOff = (c & 1) ? B1_OFF : B0_OFF;

        if (c < 7) {
            const uint32_t nOff = (c & 1) ? B0_OFF : B1_OFF;
            const uint4* esrc = (const uint4*)(g_eh + ((size_t)(nc0 + 128) << 8));
            #pragma unroll 2
            for (int i = tid; i < 4096; i += 512) {
                int row = i >> 5, kb = i & 31;
                CP_ASYNC16(sb + nOff + row * 512 + ((kb ^ (row & 7)) << 4), esrc + i);
            }
            CP_COMMIT();
        }

        float acc[8][4];
        #pragma unroll
        for (int nt = 0; nt < 8; ++nt)
            #pragma unroll
            for (int q = 0; q < 4; ++q) acc[nt][q] = 0.0f;

        #pragma unroll
        for (int s = 0; s < 16; ++s) {
            uint32_t a0, a1, a2, a3;
            int ach = 2 * s + akc;
            LDSM_X4(a0, a1, a2, a3, aBase + (uint32_t)((ach ^ (arow & 7)) << 4));
            #pragma unroll
            for (int p = 0; p < 4; ++p) {
                int brow = nb0 + (p << 4) + brow_off;
                int bch  = 2 * s + bkc;
                uint32_t b0, b1, b2, b3;
                LDSM_X4(b0, b1, b2, b3,
                        sb + bOff + (uint32_t)brow * 512
                                  + (uint32_t)((bch ^ (brow & 7)) << 4));
                MMA16816(acc[2 * p],     a0, a1, a2, a3, b0, b1);
                MMA16816(acc[2 * p + 1], a0, a1, a2, a3, b2, b3);
            }
        }

        // Two half-passes: warps with ch==h stage their 64 cols of da to
        // smem (identical fp16 da arithmetic to R14/R15), then filter threads
        // scan. Filter and next-half staging are barrier-separated.
        #pragma unroll
        for (int h = 0; h < 2; ++h) {
            if (ch == h) {
                int r0l = m0 + (lane >> 2);
                int cb = (lane & 3) << 1;
                #pragma unroll
                for (int nt = 0; nt < 8; ++nt) {
                    int coll = (nt << 3) + cb;                 // 0..63 local
                    float e20 = es2s[nc0 + (h << 6) + coll];
                    float e21 = es2s[nc0 + (h << 6) + coll + 1];
                    __half2 v0 = __floats2half2_rn(fmaf(-2.0f, acc[nt][0], e20),
                                                   fmaf(-2.0f, acc[nt][1], e21));
                    __half2 v1 = __floats2half2_rn(fmaf(-2.0f, acc[nt][2], e20),
                                                   fmaf(-2.0f, acc[nt][3], e21));
                    *(__half2*)&S[r0l * S_STRIDE + coll]       = v0;
                    *(__half2*)&S[(r0l + 8) * S_STRIDE + coll] = v1;
                }
            }
            __syncthreads();
            if (tid < 128) {
                const __half* srow = &S[tid * S_STRIDE];
                const int cbase = nc0 + (h << 6);
                #pragma unroll 4
                for (int q = 0; q < 64; ++q) {
                    float da = __half2float(srow[q]);
                    if (da < best) best = da;
                    if (da <= best + margin) {
                        if (ncand == CAP) {
                            int m2 = 0;
                            #pragma unroll
                            for (int s2 = 0; s2 < CAP; ++s2) {
                                float v = cval[s2 * 128 + tid];
                                if (v <= best + margin) {
                                    if (m2 != s2) {
                                        cval[m2 * 128 + tid]  = v;
                                        ccode[m2 * 128 + tid] = ccode[s2 * 128 + tid];
                                    }
                                    ++m2;
                                }
                            }
                            ncand = m2;
                        }
                        if (ncand < CAP) {
                            cval[ncand * 128 + tid]  = da;
                            ccode[ncand * 128 + tid] = (unsigned short)(cbase + q);
                            ++ncand;
                        } else {
                            ovf = true;
                        }
                    }
                }
            }
            __syncthreads();
        }

        if (c < 7) CP_WAIT0();   // next B landed (barrier above ordered reads)
    }

    // Final prune against the global best + writeout.
    if (tid < 128) {
        int tok = tok0 + tid;
        if (ovf) {
            g_ncand[tok] = 255;
        } else {
            int m2 = 0;
            for (int s2 = 0; s2 < ncand; ++s2) {
                float v = cval[s2 * 128 + tid];
                if (v <= best + margin) {
                    ccode[m2 * 128 + tid] = ccode[s2 * 128 + tid];
                    ++m2;
                }
            }
            g_ncand[tok] = (unsigned char)m2;
            for (int s2 = 0; s2 < m2; ++s2)
                g_cand[(size_t)tok * CAP + s2] = ccode[s2 * 128 + tid];
        }
    }
}

// ===========================================================================
// Kernel 3: warp-per-token exact rescore of candidates.
// n==1 (majority): direct write, no memory traffic. n<=CAP: lane-parallel
// exact rescore + (dist, lowest-code) reduce. n==255: warp-parallel exact
// full scan (R13-validated).
// ===========================================================================
__global__ void __launch_bounds__(256) vq_rescore_kernel(const float* __restrict__ emb) {
    const int warp = threadIdx.x >> 5, lane = threadIdx.x & 31;
    const int tok = (blockIdx.x << 3) + warp;
    const int n = g_ncand[tok];
    if (n == 1) {
        if (lane == 0) g_idx[tok] = g_cand[(size_t)tok * CAP];
        return;
    }
    const float r2 = g_r2[tok];
    const float* zr = g_zt + (size_t)tok * DD;
    float bd = CUDART_INF_F;
    int   bc = 0x7fffffff;

    if (n <= CAP) {
        if (lane < n) {
            int code = g_cand[(size_t)tok * CAP + lane];
            bd = exact_dist(zr, emb + ((size_t)code << 8), r2, g_e2[code]);
            bc = code;
        }
    } else {
        // Warp-parallel exact full scan (validated R13).
        #pragma unroll 1
        for (int s = 0; s < 32; ++s) {
            int code = (lane << 5) + s;
            float dist = exact_dist(zr, emb + ((size_t)code << 8),
                                    r2, g_e2[code]);
            if (dist < bd) { bd = dist; bc = code; }
        }
    }
    #pragma unroll
    for (int d = 16; d > 0; d >>= 1) {
        float od = __shfl_xor_sync(0xffffffffu, bd, d);
        int   oc = __shfl_xor_sync(0xffffffffu, bc, d);
        if (od < bd || (od == bd && oc < bc)) { bd = od; bc = oc; }
    }
    if (lane == 0) g_idx[tok] = bc;
}

// ===========================================================================
// Kernel 4: gather + straight-through output + loss partial sums (float4,
// measured 78us). out = fl(z + fl(q - z)); loss fl((q-z)^2) in double.
// ===========================================================================
__global__ void vq_output_kernel(const float* __restrict__ z,
                                 const float* __restrict__ emb,
                                 float* __restrict__ out) {
    double local = 0.0;
    const size_t nvec = NDATA >> 2;
    const size_t stride = (size_t)gridDim.x * blockDim.x;
    for (size_t i = (size_t)blockIdx.x * blockDim.x + threadIdx.x; i < nvec; i += stride) {
        size_t e = i << 2;
        int t  = (int)(e & 4095);
        int d  = (int)((e >> 12) & 255);
        int bb = (int)(e >> 20);
        int4 idx = *(const int4*)&g_idx[(bb << 12) + t];
        float4 zv = *(const float4*)&z[e];
        float q0 = __ldg(&emb[((size_t)idx.x << 8) + d]);
        float q1 = __ldg(&emb[((size_t)idx.y << 8) + d]);
        float q2 = __ldg(&emb[((size_t)idx.z << 8) + d]);
        float q3 = __ldg(&emb[((size_t)idx.w << 8) + d]);
        float d0 = __fsub_rn(q0, zv.x), d1 = __fsub_rn(q1, zv.y);
        float d2 = __fsub_rn(q2, zv.z), d3 = __fsub_rn(q3, zv.w);
        float4 ov = make_float4(__fadd_rn(zv.x, d0), __fadd_rn(zv.y, d1),
                                __fadd_rn(zv.z, d2), __fadd_rn(zv.w, d3));
        *(float4*)&out[e] = ov;
        local += (double)__fmul_rn(d0, d0) + (double)__fmul_rn(d1, d1)
               + (double)__fmul_rn(d2, d2) + (double)__fmul_rn(d3, d3);
    }
    #pragma unroll
    for (int off = 16; off > 0; off >>= 1)
        local += __shfl_down_sync(0xffffffffu, local, off);
    __shared__ double wsum[8];
    int lane = threadIdx.x & 31, wid = threadIdx.x >> 5;
    if (lane == 0) wsum[wid] = local;
    __syncthreads();
    if (threadIdx.x == 0) {
        double s = 0.0;
        #pragma unroll
        for (int i = 0; i < 8; ++i) s += wsum[i];
        atomicAdd(&g_loss_sum, s);
    }
}

// ===========================================================================
// Kernel 5: finalize loss = fl(m + fl(0.25*m)).
// ===========================================================================
__global__ void vq_finalize_kernel(float* __restrict__ out, int out_size) {
    if (threadIdx.x == 0 && blockIdx.x == 0) {
        if ((size_t)out_size > NDATA) {
            float m = (float)(g_loss_sum * (1.0 / 16777216.0));
            out[NDATA] = __fadd_rn(m, __fmul_rn(0.25f, m));
        }
    }
}

// ===========================================================================
extern "C" void kernel_launch(void* const* d_in, const int* in_sizes, int n_in,
                              void* d_out, int out_size) {
    const float* z   = (const float*)d_in[0];
    const float* emb = (const float*)d_in[1];
    if (n_in >= 2 && in_sizes[0] == KK * DD && (size_t)in_sizes[1] == NDATA) {
        const float* tmp = z; z = emb; emb = tmp;
    }
    float* out = (float*)d_out;

    cudaFuncSetAttribute((const void*)vq_mma_kernel,
                         cudaFuncAttributeMaxDynamicSharedMemorySize, SMEM_TOT);

    vq_prep_kernel<<<4, 256>>>(emb);
    vq_convert_r2_kernel<<<NTOK / 32, 256>>>(z);
    vq_mma_kernel<<<NTOK / 128, 512, SMEM_TOT>>>();
    vq_rescore_kernel<<<NTOK / 8, 256>>>(emb);
    vq_output_kernel<<<2048, 256>>>(z, emb, out);
    vq_finalize_kernel<<<1, 32>>>(out, out_size);
}

// round 17
// speedup vs baseline: 1.6250x; 1.6250x over previous
#include <cuda_runtime.h>
#include <cuda_fp16.h>
#include <math_constants.h>
#include <cstdint>

// Problem constants
#define DD 256
#define TT 4096
#define BBATCH 16
#define KK 1024
#define NTOK (BBATCH * TT)                  // 65536 tokens
#define NDATA ((size_t)BBATCH * DD * TT)    // 16777216 output data elements

// Scratch (no cudaMalloc allowed)
__device__ float          g_e2[KK];
__device__ float          g_r2[NTOK];
__device__ int            g_idx[NTOK];
__device__ double         g_loss_sum;
__device__ float          g_zt[NDATA];          // z transposed [token][d] fp32
__device__ __half         g_zh[NDATA];          // z transposed fp16
__device__ __half         g_eh[KK * DD];        // emb fp16
__device__ __half         g_dah[(size_t)NTOK * KK];  // approx dists fp16 (128 MB)

__device__ __forceinline__ uint32_t s2u(const void* p) {
    uint32_t a;
    asm("{ .reg .u64 t; cvta.to.shared.u64 t, %1; cvt.u32.u64 %0, t; }"
        : "=r"(a) : "l"(p));
    return a;
}

#define LDSM_X4(r0, r1, r2, r3, addr)                                          \
    asm volatile("ldmatrix.sync.aligned.m8n8.x4.shared.b16 {%0,%1,%2,%3}, [%4];" \
                 : "=r"(r0), "=r"(r1), "=r"(r2), "=r"(r3) : "r"(addr))

// fp16 HMMA (validated R14/R15), u=2^-11.
#define MMA16816(d, a0, a1, a2, a3, b0, b1)                                    \
    asm volatile("mma.sync.aligned.m16n8k16.row.col.f32.f16.f16.f32 "          \
                 "{%0,%1,%2,%3}, {%4,%5,%6,%7}, {%8,%9}, {%0,%1,%2,%3};"       \
                 : "+f"((d)[0]), "+f"((d)[1]), "+f"((d)[2]), "+f"((d)[3])      \
                 : "r"(a0), "r"(a1), "r"(a2), "r"(a3), "r"(b0), "r"(b1))

#define CP_ASYNC16(dst, src)                                                   \
    asm volatile("cp.async.cg.shared.global [%0], [%1], 16;"                   \
                 :: "r"(dst), "l"(src))
#define CP_COMMIT() asm volatile("cp.async.commit_group;" ::: "memory")
#define CP_WAIT0()  asm volatile("cp.async.wait_group 0;" ::: "memory")

// Exact rescore of one code: sequential ascending-d fused fmaf (bit-matches
// the reference; validated R2/R7/R13/R14/R15).
__device__ __forceinline__ float exact_dist(const float* __restrict__ zr,
                                            const float* __restrict__ er,
                                            float r2, float e2) {
    float acc = 0.0f;
    #pragma unroll 8
    for (int d = 0; d < DD; d += 4) {
        float4 z4 = *(const float4*)&zr[d];
        float4 e4 = __ldg((const float4*)&er[d]);
        acc = fmaf(z4.x, e4.x, acc);
        acc = fmaf(z4.y, e4.y, acc);
        acc = fmaf(z4.z, e4.z, acc);
        acc = fmaf(z4.w, e4.w, acc);
    }
    return __fsub_rn(__fadd_rn(r2, e2), __fmul_rn(2.0f, acc));
}

// ===========================================================================
// Kernel 0: exact ||e_k||^2 (sequential mul-then-add) + fp16 convert + zero loss
// ===========================================================================
__global__ void vq_prep_kernel(const float* __restrict__ emb) {
    int k = blockIdx.x * blockDim.x + threadIdx.x;
    if (k == 0) g_loss_sum = 0.0;
    if (k < KK) {
        const float* e = emb + (size_t)k * DD;
        float acc = 0.0f;
        #pragma unroll 8
        for (int d = 0; d < DD; ++d) {
            float v = e[d];
            acc = __fadd_rn(acc, __fmul_rn(v, v));
            g_eh[(size_t)k * DD + d] = __float2half_rn(v);
        }
        g_e2[k] = acc;
    }
}

// ===========================================================================
// Kernel 1: FUSED transpose (zt fp32 + zh fp16) + exact r2 (R15 winner).
// ===========================================================================
__global__ void __launch_bounds__(256) vq_convert_r2_kernel(const float* __restrict__ z) {
    __shared__ float tile[256][33];
    const int b = blockIdx.x >> 7, t0 = (blockIdx.x & 127) << 5;
    const int tid = threadIdx.x;
    const int tx = tid & 31, ty = tid >> 5;           // 32 x 8
    const float* src = z + (size_t)b * DD * TT + t0;
    #pragma unroll
    for (int k = 0; k < 32; ++k) {
        int d = ty + (k << 3);
        tile[d][tx] = src[(size_t)d * TT + tx];
    }
    __syncthreads();

    const int tok = tid >> 3, q = tid & 7;
    const size_t base = ((size_t)((b << 12) + t0 + tok)) * DD;
    #pragma unroll
    for (int jj = 0; jj < 8; ++jj) {
        int d0 = (jj << 5) + (q << 2);
        float4 v = make_float4(tile[d0][tok], tile[d0 + 1][tok],
                               tile[d0 + 2][tok], tile[d0 + 3][tok]);
        *(float4*)&g_zt[base + d0] = v;
        __half2 h01 = __floats2half2_rn(v.x, v.y);
        __half2 h23 = __floats2half2_rn(v.z, v.w);
        *(__half2*)&g_zh[base + d0]     = h01;
        *(__half2*)&g_zh[base + d0 + 2] = h23;
    }

    if (tid < 32) {
        float acc = 0.0f;
        #pragma unroll 8
        for (int d = 0; d < DD; ++d) {
            float v = tile[d][tid];
            acc = __fadd_rn(acc, __fmul_rn(v, v));
        }
        g_r2[(b << 12) + t0 + tid] = acc;
    }
}

// ===========================================================================
// Kernel 2: fp16 HMMA approx-dist GEMM (R14/R15 winner, 147us measured).
// cp.async double-buffered B; fp16 epilogue.
// ===========================================================================
#define ES2_OFF 0                      // 4096 B
#define A_OFF   4096                   // 65536 B
#define B0_OFF  69632                  // 65536 B
#define B1_OFF  135168                 // 65536 B
#define SMEM_TOT 200704

__global__ void __launch_bounds__(512, 1) vq_mma_kernel() {
    extern __shared__ char smem[];
    const uint32_t sb = s2u(smem);
    const int tid = threadIdx.x, wid = tid >> 5, lane = tid & 31;
    const int tok0 = blockIdx.x << 7;
    float* es2s = (float*)(smem + ES2_OFF);

    es2s[tid]       = g_e2[tid];
    es2s[tid + 512] = g_e2[tid + 512];

    const uint4* zsrc = (const uint4*)(g_zh + ((size_t)tok0 << 8));
    #pragma unroll 2
    for (int i = tid; i < 4096; i += 512) {
        int row = i >> 5, kb = i & 31;
        CP_ASYNC16(sb + A_OFF + row * 512 + ((kb ^ (row & 7)) << 4), zsrc + i);
    }
    {
        const uint4* esrc = (const uint4*)g_eh;
        #pragma unroll 2
        for (int i = tid; i < 4096; i += 512) {
            int row = i >> 5, kb = i & 31;
            CP_ASYNC16(sb + B0_OFF + row * 512 + ((kb ^ (row & 7)) << 4), esrc + i);
        }
    }
    CP_COMMIT();
    CP_WAIT0();
    __syncthreads();

    const int rg = wid & 7, ch = wid >> 3;
    const int m0 = rg << 4, nb0 = ch << 6;
    const int lr = lane & 7;
    const int arow = m0 + lr + (((lane >> 3) & 1) << 3);
    const int akc  = lane >> 4;
    const int brow_off = lr + ((lane >> 4) << 3);
    const int bkc  = (lane >> 3) & 1;
    const uint32_t aBase = sb + A_OFF + (uint32_t)arow * 512;

    for (int c = 0; c < 8; ++c) {
        const int nc0 = c << 7;
        const uint32_t bOff = (c & 1) ? B1_OFF : B0_OFF;

        if (c < 7) {
            const uint32_t nOff = (c & 1) ? B0_OFF : B1_OFF;
            const uint4* esrc = (const uint4*)(g_eh + ((size_t)(nc0 + 128) << 8));
            #pragma unroll 2
            for (int i = tid; i < 4096; i += 512) {
                int row = i >> 5, kb = i & 31;
                CP_ASYNC16(sb + nOff + row * 512 + ((kb ^ (row & 7)) << 4), esrc + i);
            }
            CP_COMMIT();
        }

        float acc[8][4];
        #pragma unroll
        for (int nt = 0; nt < 8; ++nt)
            #pragma unroll
            for (int q = 0; q < 4; ++q) acc[nt][q] = 0.0f;

        #pragma unroll
        for (int s = 0; s < 16; ++s) {
            uint32_t a0, a1, a2, a3;
            int ach = 2 * s + akc;
            LDSM_X4(a0, a1, a2, a3, aBase + (uint32_t)((ach ^ (arow & 7)) << 4));
            #pragma unroll
            for (int p = 0; p < 4; ++p) {
                int brow = nb0 + (p << 4) + brow_off;
                int bch  = 2 * s + bkc;
                uint32_t b0, b1, b2, b3;
                LDSM_X4(b0, b1, b2, b3,
                        sb + bOff + (uint32_t)brow * 512
                                  + (uint32_t)((bch ^ (brow & 7)) << 4));
                MMA16816(acc[2 * p],     a0, a1, a2, a3, b0, b1);
                MMA16816(acc[2 * p + 1], a0, a1, a2, a3, b2, b3);
            }
        }

        {
            int r0 = tok0 + m0 + (lane >> 2);
            int cb = (lane & 3) << 1;
            #pragma unroll
            for (int nt = 0; nt < 8; ++nt) {
                int col = nb0 + (nt << 3) + cb;
                float e20 = es2s[nc0 + col];
                float e21 = es2s[nc0 + col + 1];
                __half2 v0 = __floats2half2_rn(fmaf(-2.0f, acc[nt][0], e20),
                                               fmaf(-2.0f, acc[nt][1], e21));
                __half2 v1 = __floats2half2_rn(fmaf(-2.0f, acc[nt][2], e20),
                                               fmaf(-2.0f, acc[nt][3], e21));
                *(__half2*)&g_dah[(size_t)r0 * KK + nc0 + col]       = v0;
                *(__half2*)&g_dah[(size_t)(r0 + 8) * KK + nc0 + col] = v1;
            }
        }

        if (c < 7) {
            CP_WAIT0();
            __syncthreads();
        }
    }
}

// ===========================================================================
// Kernel 3: warp-per-token select + exact rescore (R15 winner logic).
// CHANGE vs R15: g_dah loaded as 4x uint4 (16B/lane, lane covers 8
// consecutive halves at i*256 + 8*lane) instead of 8x uint2 -- same perfect
// coalescing, half the load instructions and address math (kernel measured
// issue-bound at 37.6%). Filter/prefix/rescore logic unchanged.
// fp16-tight margin: dist_err <= 3.1e-5*||z||; margin = 8e-5*||z|| + 6e-4.
// Fallback >32 candidates: warp-parallel exact full scan (R13-validated).
// ===========================================================================
__global__ void __launch_bounds__(256) vq_select_kernel(const float* __restrict__ emb) {
    const int warp = threadIdx.x >> 5, lane = threadIdx.x & 31;
    const int tok = (blockIdx.x << 3) + warp;
    const __half* da = g_dah + (size_t)tok * KK;

    // 4 x uint4 = 32 halves per lane; chunk i covers codes i*256 + lane*8 + 0..7.
    float2 f[16];                       // 32 values as float2 pairs
    float mn = CUDART_INF_F;
    #pragma unroll
    for (int i = 0; i < 4; ++i) {
        uint4 h = *(const uint4*)(da + (i << 8) + (lane << 3));
        f[i * 4 + 0] = __half22float2(*(const __half2*)&h.x);
        f[i * 4 + 1] = __half22float2(*(const __half2*)&h.y);
        f[i * 4 + 2] = __half22float2(*(const __half2*)&h.z);
        f[i * 4 + 3] = __half22float2(*(const __half2*)&h.w);
    }
    #pragma unroll
    for (int j = 0; j < 16; ++j)
        mn = fminf(mn, fminf(f[j].x, f[j].y));
    #pragma unroll
    for (int off = 16; off > 0; off >>= 1)
        mn = fminf(mn, __shfl_xor_sync(0xffffffffu, mn, off));

    const float r2 = g_r2[tok];
    const float thr = mn + fmaf(8e-5f, sqrtf(r2), 6e-4f);

    int cnt = 0;
    #pragma unroll
    for (int j = 0; j < 16; ++j)
        cnt += (f[j].x <= thr) + (f[j].y <= thr);
    int off = cnt;
    #pragma unroll
    for (int d = 1; d < 32; d <<= 1) {
        int t2 = __shfl_up_sync(0xffffffffu, off, d);
        if (lane >= d) off += t2;
    }
    const int total = __shfl_sync(0xffffffffu, off, 31);
    const int excl = off - cnt;

    __shared__ unsigned short clist[8][36];
    const float* zr = g_zt + (size_t)tok * DD;

    float bd = CUDART_INF_F;
    int   bc = 0x7fffffff;

    if (total <= 32) {
        int k = excl;
        #pragma unroll
        for (int j = 0; j < 16; ++j) {
            // code of f[j].x: chunk i=j>>2, word w=j&3 -> i*256 + lane*8 + w*2
            int base = ((j >> 2) << 8) + (lane << 3) + ((j & 3) << 1);
            if (f[j].x <= thr) clist[warp][k++] = (unsigned short)(base + 0);
            if (f[j].y <= thr) clist[warp][k++] = (unsigned short)(base + 1);
        }
        __syncwarp();
        if (lane < total) {
            int code = clist[warp][lane];
            bd = exact_dist(zr, emb + ((size_t)code << 8), r2, g_e2[code]);
            bc = code;
        }
    } else {
        // Warp-parallel exact full scan (validated R13).
        #pragma unroll 1
        for (int s = 0; s < 32; ++s) {
            int code = (lane << 5) + s;
            float dist = exact_dist(zr, emb + ((size_t)code << 8),
                                    r2, g_e2[code]);
            if (dist < bd) { bd = dist; bc = code; }
        }
    }
    #pragma unroll
    for (int d = 16; d > 0; d >>= 1) {
        float od = __shfl_xor_sync(0xffffffffu, bd, d);
        int   oc = __shfl_xor_sync(0xffffffffu, bc, d);
        if (od < bd || (od == bd && oc < bc)) { bd = od; bc = oc; }
    }
    if (lane == 0) g_idx[tok] = bc;
}

// ===========================================================================
// Kernel 4: gather + straight-through output + loss partial sums (float4,
// measured 78us). out = fl(z + fl(q - z)); loss fl((q-z)^2) in double.
// ===========================================================================
__global__ void vq_output_kernel(const float* __restrict__ z,
                                 const float* __restrict__ emb,
                                 float* __restrict__ out) {
    double local = 0.0;
    const size_t nvec = NDATA >> 2;
    const size_t stride = (size_t)gridDim.x * blockDim.x;
    for (size_t i = (size_t)blockIdx.x * blockDim.x + threadIdx.x; i < nvec; i += stride) {
        size_t e = i << 2;
        int t  = (int)(e & 4095);
        int d  = (int)((e >> 12) & 255);
        int bb = (int)(e >> 20);
        int4 idx = *(const int4*)&g_idx[(bb << 12) + t];
        float4 zv = *(const float4*)&z[e];
        float q0 = __ldg(&emb[((size_t)idx.x << 8) + d]);
        float q1 = __ldg(&emb[((size_t)idx.y << 8) + d]);
        float q2 = __ldg(&emb[((size_t)idx.z << 8) + d]);
        float q3 = __ldg(&emb[((size_t)idx.w << 8) + d]);
        float d0 = __fsub_rn(q0, zv.x), d1 = __fsub_rn(q1, zv.y);
        float d2 = __fsub_rn(q2, zv.z), d3 = __fsub_rn(q3, zv.w);
        float4 ov = make_float4(__fadd_rn(zv.x, d0), __fadd_rn(zv.y, d1),
                                __fadd_rn(zv.z, d2), __fadd_rn(zv.w, d3));
        *(float4*)&out[e] = ov;
        local += (double)__fmul_rn(d0, d0) + (double)__fmul_rn(d1, d1)
               + (double)__fmul_rn(d2, d2) + (double)__fmul_rn(d3, d3);
    }
    #pragma unroll
    for (int off = 16; off > 0; off >>= 1)
        local += __shfl_down_sync(0xffffffffu, local, off);
    __shared__ double wsum[8];
    int lane = threadIdx.x & 31, wid = threadIdx.x >> 5;
    if (lane == 0) wsum[wid] = local;
    __syncthreads();
    if (threadIdx.x == 0) {
        double s = 0.0;
        #pragma unroll
        for (int i = 0; i < 8; ++i) s += wsum[i];
        atomicAdd(&g_loss_sum, s);
    }
}

// ===========================================================================
// Kernel 5: finalize loss = fl(m + fl(0.25*m)).
// ===========================================================================
__global__ void vq_finalize_kernel(float* __restrict__ out, int out_size) {
    if (threadIdx.x == 0 && blockIdx.x == 0) {
        if ((size_t)out_size > NDATA) {
            float m = (float)(g_loss_sum * (1.0 / 16777216.0));
            out[NDATA] = __fadd_rn(m, __fmul_rn(0.25f, m));
        }
    }
}

// ===========================================================================
extern "C" void kernel_launch(void* const* d_in, const int* in_sizes, int n_in,
                              void* d_out, int out_size) {
    const float* z   = (const float*)d_in[0];
    const float* emb = (const float*)d_in[1];
    if (n_in >= 2 && in_sizes[0] == KK * DD && (size_t)in_sizes[1] == NDATA) {
        const float* tmp = z; z = emb; emb = tmp;
    }
    float* out = (float*)d_out;

    cudaFuncSetAttribute((const void*)vq_mma_kernel,
                         cudaFuncAttributeMaxDynamicSharedMemorySize, SMEM_TOT);

    vq_prep_kernel<<<4, 256>>>(emb);
    vq_convert_r2_kernel<<<NTOK / 32, 256>>>(z);
    vq_mma_kernel<<<NTOK / 128, 512, SMEM_TOT>>>();
    vq_select_kernel<<<NTOK / 8, 256>>>(emb);
    vq_output_kernel<<<2048, 256>>>(z, emb, out);
    vq_finalize_kernel<<<1, 32>>>(out, out_size);
}